// round 11
// baseline (speedup 1.0000x reference)
#include <cuda_runtime.h>
#include <cstdint>

#define BB     64
#define TT_    2000
#define AA     256
#define FF     32
#define KK     31
#define TILE   100
#define NTIL   20
#define NTILES (BB * NTIL)
#define NPR    66
#define SPLIT  8
#define SLICE  (TT_ / SPLIT)         // 250
#define C2L    2.8853900817779268f   // 2*log2(e)
#define NEGINF (-3.402823466e38f)

typedef unsigned long long ull;

// Scratch (no allocations allowed)
__device__ float g_W2s[KK * AA];     // W2 rows 0..30, pre-scaled by C2L
__device__ float g_qadd[AA];         // score_b + conv_b @ loc_w
__device__ float g_energy[BB * TT_];
__device__ float g_pmax[NTILES];     // per-tile max   [b * NTIL + tix]
__device__ float g_psum[NTILES];     // per-tile sum   [b * NTIL + tix]
__device__ int   g_w2_done;          // 0 -> 32 within a run; reset by normalize

__device__ __forceinline__ ull pk(float lo, float hi) {
    return ((ull)__float_as_uint(hi) << 32) | (ull)__float_as_uint(lo);
}
#define FMA2(acc, p, w) asm("fma.rn.f32x2 %0, %1, %2, %0;" : "+l"(acc) : "l"(p), "l"(w))

// ---------------------------------------------------------------------------
// Energy kernel (grid NTILES, dynamic HW scheduling).
// Blocks 0..31 first compute one W2 row each (row 31 = bias fold), then all
// blocks process their (b, tile) and emit per-tile softmax partials.
// ---------------------------------------------------------------------------
__global__ void __launch_bounds__(256, 4) energy_kernel(
    const float* __restrict__ query,
    const float* __restrict__ pw,
    const float* __restrict__ wmem,
    const int*   __restrict__ lens,
    const float* __restrict__ cw,
    const float* __restrict__ cb,
    const float* __restrict__ lw,
    const float* __restrict__ sv,
    const float* __restrict__ sb) {

    __shared__ float s_c[FF];
    __shared__ float Wf[140];
    __shared__ __align__(16) ull Esh[NPR];
    __shared__ __align__(16) ull Osh[NPR];
    __shared__ float4 Wsum4[8][TILE];            // 4 partials per (warp, t)
    __shared__ float s_red[8];
    __shared__ float s_m;

    const int tid  = threadIdx.x;
    const int bid  = blockIdx.x;
    const int a    = tid;
    const int lane = tid & 31, warp = tid >> 5;

    // -------- W2 phase (blocks 0..31 only) --------------------------------
    if (bid < 32) {
        if (tid < FF) s_c[tid] = (bid < KK) ? cw[bid * FF + tid] : cb[tid];
        __syncthreads();
        float s = 0.f;
        #pragma unroll
        for (int f = 0; f < FF; ++f) s = fmaf(s_c[f], lw[f * AA + a], s);
        if (bid < KK) g_W2s[bid * AA + a] = s * C2L;
        else          g_qadd[a] = sb[a] + s;
        __threadfence();
        __syncthreads();
        if (tid == 0) atomicAdd(&g_w2_done, 1);
    }

    // -------- Tile setup (no W2 dependency yet) ---------------------------
    const int b   = bid & 63;
    const int tix = bid >> 6;
    const int len = lens[b];
    const int t0  = tix * TILE;
    if (t0 >= len) return;                       // fully masked: skip
    const int n   = min(t0 + TILE, len) - t0;
    const int n4  = (n + 3) & ~3;

    // Stage pw window in smem (one LDG per element), then build pair arrays:
    // Esh[j]=(W[2j],W[2j+1])  Osh[j]=(W[2j+1],W[2j+2]),  W[i]=pw[b,t0-15+i]
    if (tid < 138) {
        const int g = t0 - 15 + tid;
        Wf[tid] = (g >= 0 && g < TT_) ? pw[b * TT_ + g] : 0.f;
    }
    __syncthreads();
    if (tid < NPR) {
        float w0 = Wf[2 * tid], w1 = Wf[2 * tid + 1], w2 = Wf[2 * tid + 2];
        Esh[tid] = pk(w0, w1);
        Osh[tid] = pk(w1, w2);
    }
    const float q   = query[b * AA + a];
    const float svv = sv[a];
    const float n2s = -2.0f * svv;

    // Prime the x-load pipeline (quad 0) before waiting on W2
    const float* xp = wmem + ((size_t)(b * TT_ + t0)) * AA + a;
    float cx0 = (0 < n) ? __ldg(xp)          : 0.f;
    float cx1 = (1 < n) ? __ldg(xp + AA)     : 0.f;
    float cx2 = (2 < n) ? __ldg(xp + 2 * AA) : 0.f;
    float cx3 = (3 < n) ? __ldg(xp + 3 * AA) : 0.f;

    // -------- Wait for W2 (replay-safe: normalize resets the counter) -----
    if (tid == 0) {
        while (*(volatile int*)&g_w2_done < 32) { __nanosleep(64); }
    }
    __syncthreads();
    __threadfence();

    // Per-thread constants (column 'a'); W2 already scaled by C2L
    const float qbp = (q + g_qadd[a]) * C2L;
    ull w2p[16];
    #pragma unroll
    for (int j = 0; j < 15; ++j)
        w2p[j] = pk(g_W2s[(2 * j) * AA + a], g_W2s[(2 * j + 1) * AA + a]);
    w2p[15] = pk(g_W2s[30 * AA + a], 0.f);

    for (int tb = 0; tb < n4; tb += 4) {
        const int m0 = tb >> 1;                  // even -> 16B-aligned pair base
        const float x0 = cx0, x1 = cx1, x2 = cx2, x3 = cx3;
        xp += 4 * AA;

        // Prefetch next quad's x values (one-quad software pipeline)
        if (tb + 4 < n4) {
            cx0 = (tb + 4 < n) ? __ldg(xp)          : 0.f;
            cx1 = (tb + 5 < n) ? __ldg(xp + AA)     : 0.f;
            cx2 = (tb + 6 < n) ? __ldg(xp + 2 * AA) : 0.f;
            cx3 = (tb + 7 < n) ? __ldg(xp + 3 * AA) : 0.f;
        }

        ull a0 = pk(fmaf(x0, C2L, qbp), 0.f);
        ull a1 = pk(fmaf(x1, C2L, qbp), 0.f);
        ull a2 = pk(fmaf(x2, C2L, qbp), 0.f);
        ull a3 = pk(fmaf(x3, C2L, qbp), 0.f);

        const ulonglong2* Ep = (const ulonglong2*)(Esh + m0);
        const ulonglong2* Op = (const ulonglong2*)(Osh + m0);
        #pragma unroll
        for (int m = 0; m < 8; ++m) {
            ulonglong2 e = Ep[m];                // LDS.128 broadcast
            FMA2(a0, e.x, w2p[2 * m]);
            FMA2(a0, e.y, w2p[2 * m + 1]);
            if (m > 0) FMA2(a2, e.x, w2p[2 * m - 1]);
            FMA2(a2, e.y, w2p[2 * m]);
            ulonglong2 o = Op[m];
            FMA2(a1, o.x, w2p[2 * m]);
            FMA2(a1, o.y, w2p[2 * m + 1]);
            if (m > 0) FMA2(a3, o.x, w2p[2 * m - 1]);
            FMA2(a3, o.y, w2p[2 * m]);
        }
        { ull e16 = Esh[m0 + 16]; FMA2(a2, e16, w2p[15]); }
        { ull o16 = Osh[m0 + 16]; FMA2(a3, o16, w2p[15]); }

        // tanh(z) = 1 - 2/(e^{2z}+1); acc holds 2z*log2(e) split lo/hi
        float p0, p1, p2, p3;
        {
            float arg, u, r;
            #define FIN(acc, dst)                                              \
                arg = __uint_as_float((unsigned)(acc)) +                       \
                      __uint_as_float((unsigned)((acc) >> 32));                \
                asm("ex2.approx.f32 %0, %1;" : "=f"(u) : "f"(arg));            \
                asm("rcp.approx.f32 %0, %1;" : "=f"(r) : "f"(u + 1.0f));       \
                dst = fmaf(n2s, r, svv);
            FIN(a0, p0); FIN(a1, p1); FIN(a2, p2); FIN(a3, p3);
            #undef FIN
        }

        // folded 4-chain warp reduction, depth 4 (7 shfl); 4 partials per t
        float s0 = p0 + __shfl_xor_sync(0xffffffffu, p0, 16);
        float s1 = p1 + __shfl_xor_sync(0xffffffffu, p1, 16);
        float s2 = p2 + __shfl_xor_sync(0xffffffffu, p2, 16);
        float s3 = p3 + __shfl_xor_sync(0xffffffffu, p3, 16);
        float q0 = (lane < 16) ? s0 : s2;
        float q1 = (lane < 16) ? s1 : s3;
        float u0 = q0 + __shfl_xor_sync(0xffffffffu, q0, 8);
        float u1 = q1 + __shfl_xor_sync(0xffffffffu, q1, 8);
        float v  = (lane & 8) ? u1 : u0;
        v += __shfl_xor_sync(0xffffffffu, v, 4);
        // octet o holds t = tb+o; lanes with (lane&4)==0 hold 4 distinct
        // partials whose sum is the full 32-lane sum. Conflict-free STS.
        if ((lane & 4) == 0)
            ((float*)&Wsum4[warp][tb + (lane >> 3)])[lane & 3] = v;
    }
    __syncthreads();

    // -------- Epilogue: write energies + per-tile softmax partials --------
    float e_val = NEGINF;
    if (tid < n) {
        float s = 0.f;
        #pragma unroll
        for (int w = 0; w < 8; ++w) {
            float4 f = Wsum4[w][tid];
            s += (f.x + f.y) + (f.z + f.w);
        }
        g_energy[b * TT_ + t0 + tid] = s;
        e_val = s;
    }
    // block max over e_val
    float m = e_val;
    #pragma unroll
    for (int o = 16; o; o >>= 1) m = fmaxf(m, __shfl_xor_sync(0xffffffffu, m, o));
    if (lane == 0) s_red[warp] = m;
    __syncthreads();
    if (tid < 32) {
        float v = (tid < 8) ? s_red[tid] : NEGINF;
        #pragma unroll
        for (int o = 4; o; o >>= 1) v = fmaxf(v, __shfl_xor_sync(0xffffffffu, v, o));
        if (tid == 0) s_m = v;
    }
    __syncthreads();
    const float tmax = s_m;
    // block sum of exp(e - tmax)
    float es = (tid < n) ? __expf(e_val - tmax) : 0.f;
    #pragma unroll
    for (int o = 16; o; o >>= 1) es += __shfl_xor_sync(0xffffffffu, es, o);
    if (lane == 0) s_red[warp] = es;
    __syncthreads();
    if (tid == 0) {
        float v = 0.f;
        #pragma unroll
        for (int w = 0; w < 8; ++w) v += s_red[w];
        g_pmax[b * NTIL + tix] = tmax;
        g_psum[b * NTIL + tix] = v;
    }
}

// ---------------------------------------------------------------------------
// Normalize (PDL secondary): prefetches pw and does setup BEFORE
// cudaGridDependencySynchronize(), then reads energy/partials after.
// Masked entries exact 0 (matches reference).
// ---------------------------------------------------------------------------
__global__ __launch_bounds__(256) void normalize_kernel(
    const float* __restrict__ pw,
    const int*   __restrict__ lens,
    float*       __restrict__ out) {

    __shared__ float s_M, s_inv;
    const int b    = blockIdx.y;
    const int sl   = blockIdx.x;
    const int tid  = threadIdx.x;

    // Pre-sync work: inputs only (pw, lens are ready before energy runs)
    const int len  = lens[b];
    const int live = (len + TILE - 1) / TILE;
    const int t      = sl * SLICE + tid;
    const bool valid = (tid < SLICE);
    float pv = 0.f;
    if (valid) pv = __ldg(pw + b * TT_ + t);

    // Wait for the energy kernel's results
    cudaGridDependencySynchronize();

    if (b == 0 && sl == 0 && tid == 0) g_w2_done = 0;   // reset for replay

    float ev = 0.f;
    if (valid) ev = __ldg(g_energy + b * TT_ + t);

    // Warp 0: parallel combine of <=NTIL tile partials
    if (tid < 32) {
        float pm = (tid < live) ? g_pmax[b * NTIL + tid] : NEGINF;
        float M = pm;
        #pragma unroll
        for (int o = 16; o; o >>= 1) M = fmaxf(M, __shfl_xor_sync(0xffffffffu, M, o));
        float ps = (tid < live) ? g_psum[b * NTIL + tid] * __expf(pm - M) : 0.f;
        #pragma unroll
        for (int o = 16; o; o >>= 1) ps += __shfl_xor_sync(0xffffffffu, ps, o);
        if (tid == 0) { s_M = M; s_inv = 1.0f / ps; }
    }
    __syncthreads();

    if (valid) {
        float w = (t < len) ? __expf(ev - s_M) * s_inv : 0.f;
        out[b * TT_ + t] = w;
        out[BB * TT_ + b * TT_ + t] = w + pv;
    }
}

// ---------------------------------------------------------------------------
extern "C" void kernel_launch(void* const* d_in, const int* in_sizes, int n_in,
                              void* d_out, int out_size) {
    const float* query  = (const float*)d_in[0];
    const float* prevw  = (const float*)d_in[1];
    const float* wmem   = (const float*)d_in[2];
    const int*   lens   = (const int*)  d_in[3];
    const float* convw  = (const float*)d_in[4];
    const float* convb  = (const float*)d_in[5];
    const float* locw   = (const float*)d_in[6];
    const float* scorev = (const float*)d_in[7];
    const float* scoreb = (const float*)d_in[8];
    float* out = (float*)d_out;

    energy_kernel<<<NTILES, 256>>>(query, prevw, wmem, lens, convw, convb, locw,
                                   scorev, scoreb);

    // PDL launch: normalize starts early; gridDepSync gates energy-dependent reads
    cudaLaunchConfig_t cfg = {};
    cfg.gridDim  = dim3(SPLIT, BB);
    cfg.blockDim = dim3(256);
    cfg.stream   = 0;
    cudaLaunchAttribute attr[1];
    attr[0].id = cudaLaunchAttributeProgrammaticStreamSerialization;
    attr[0].val.programmaticStreamSerializationAllowed = 1;
    cfg.attrs    = attr;
    cfg.numAttrs = 1;
    cudaLaunchKernelEx(&cfg, normalize_kernel, prevw, lens, out);
}

// round 13
// speedup vs baseline: 1.0915x; 1.0915x over previous
#include <cuda_runtime.h>
#include <cstdint>

#define BB     64
#define TT_    2000
#define AA     256
#define FF     32
#define KK     31
#define TILE   100
#define TILEP  104                   // padded for 8-t groups
#define NTIL   20
#define NTILES (BB * NTIL)
#define NPR    68                    // pair arrays: max read index m0+19 = 67
#define C2L    2.8853900817779268f   // 2*log2(e)
#define NEGINF (-3.402823466e38f)

typedef unsigned long long ull;

// Scratch (no allocations allowed)
__device__ float g_W2s[KK * AA];     // W2 rows 0..30, pre-scaled by C2L
__device__ float g_qadd[AA];         // score_b + conv_b @ loc_w
__device__ float g_energy[BB * TT_];
__device__ float g_pmax[NTILES];     // per-tile max   [b * NTIL + tix]
__device__ float g_psum[NTILES];     // per-tile sum   [b * NTIL + tix]
__device__ int   g_w2_done;          // 0 -> 32 within a run; reset by normalize

__device__ __forceinline__ ull pk(float lo, float hi) {
    return ((ull)__float_as_uint(hi) << 32) | (ull)__float_as_uint(lo);
}
#define FMA2(acc, p, w) asm("fma.rn.f32x2 %0, %1, %2, %0;" : "+l"(acc) : "l"(p), "l"(w))

// ---------------------------------------------------------------------------
// Energy kernel (grid NTILES). Blocks 0..31 compute W2 rows first; all blocks
// then process one (b, 100-t tile) in 8-t groups sharing window LDS, and emit
// per-tile softmax partials.
// acc[i] (t = tb+i): even i read Esh, odd i read Osh; window pair p in
// [d, d+15] (d = i/2) contributes with weight w2p[p-d].
// ---------------------------------------------------------------------------
__global__ void __launch_bounds__(256, 3) energy_kernel(
    const float* __restrict__ query,
    const float* __restrict__ pw,
    const float* __restrict__ wmem,
    const int*   __restrict__ lens,
    const float* __restrict__ cw,
    const float* __restrict__ cb,
    const float* __restrict__ lw,
    const float* __restrict__ sv,
    const float* __restrict__ sb) {

    __shared__ float s_c[FF];
    __shared__ float Wf[140];
    __shared__ __align__(16) ull Esh[NPR];
    __shared__ __align__(16) ull Osh[NPR];
    __shared__ float4 Wsum4[8][TILEP];           // 4 partials per (warp, t)
    __shared__ float s_red[8];
    __shared__ float s_m;

    const int tid  = threadIdx.x;
    const int bid  = blockIdx.x;
    const int a    = tid;
    const int lane = tid & 31, warp = tid >> 5;

    // -------- W2 phase (blocks 0..31 only) --------------------------------
    if (bid < 32) {
        if (tid < FF) s_c[tid] = (bid < KK) ? cw[bid * FF + tid] : cb[tid];
        __syncthreads();
        float s = 0.f;
        #pragma unroll
        for (int f = 0; f < FF; ++f) s = fmaf(s_c[f], lw[f * AA + a], s);
        if (bid < KK) g_W2s[bid * AA + a] = s * C2L;
        else          g_qadd[a] = sb[a] + s;
        __threadfence();
        __syncthreads();
        if (tid == 0) atomicAdd(&g_w2_done, 1);
    }

    // -------- Tile setup (no W2 dependency yet) ---------------------------
    const int b   = bid & 63;
    const int tix = bid >> 6;
    const int len = lens[b];
    const int t0  = tix * TILE;
    if (t0 >= len) return;                       // fully masked: skip
    const int n   = min(t0 + TILE, len) - t0;
    const int n8  = (n + 7) & ~7;

    // Stage pw window, build pair arrays:
    // Esh[j]=(W[2j],W[2j+1])  Osh[j]=(W[2j+1],W[2j+2]),  W[i]=pw[b,t0-15+i]
    if (tid < 138) {
        const int g = t0 - 15 + tid;
        Wf[tid] = (g >= 0 && g < TT_) ? pw[b * TT_ + g] : 0.f;
    }
    __syncthreads();
    if (tid < NPR) {
        float w0 = Wf[2 * tid], w1 = Wf[2 * tid + 1];
        float w2 = (2 * tid + 2 < 140) ? Wf[2 * tid + 2] : 0.f;
        Esh[tid] = pk(w0, w1);
        Osh[tid] = pk(w1, w2);
    }
    const float q   = query[b * AA + a];
    const float svv = sv[a];
    const float n2s = -2.0f * svv;

    // Prime one 8-group of x loads before waiting on W2
    const float* xp = wmem + ((size_t)(b * TT_ + t0)) * AA + a;
    float cx[8];
    #pragma unroll
    for (int i = 0; i < 8; ++i) cx[i] = (i < n) ? __ldg(xp + i * AA) : 0.f;
    xp += 8 * AA;

    // -------- Wait for W2 (replay-safe: normalize resets the counter) -----
    if (tid == 0) {
        while (*(volatile int*)&g_w2_done < 32) { __nanosleep(64); }
    }
    __syncthreads();
    __threadfence();

    // Per-thread constants (column 'a'); W2 already scaled by C2L
    const float qbp = (q + g_qadd[a]) * C2L;
    ull w2p[16];
    #pragma unroll
    for (int j = 0; j < 15; ++j)
        w2p[j] = pk(g_W2s[(2 * j) * AA + a], g_W2s[(2 * j + 1) * AA + a]);
    w2p[15] = pk(g_W2s[30 * AA + a], 0.f);

    for (int tb = 0; tb < n8; tb += 8) {
        const int m0 = tb >> 1;
        float x[8];
        #pragma unroll
        for (int i = 0; i < 8; ++i) x[i] = cx[i];
        // Prefetch next 8-group
        if (tb + 8 < n8) {
            #pragma unroll
            for (int i = 0; i < 8; ++i)
                cx[i] = (tb + 8 + i < n) ? __ldg(xp + i * AA) : 0.f;
        }
        xp += 8 * AA;

        ull acc[8];
        #pragma unroll
        for (int i = 0; i < 8; ++i) acc[i] = pk(fmaf(x[i], C2L, qbp), 0.f);

        const ulonglong2* Ep = (const ulonglong2*)(Esh + m0);
        const ulonglong2* Op = (const ulonglong2*)(Osh + m0);
        #pragma unroll
        for (int j = 0; j < 10; ++j) {           // pairs p = 2j, 2j+1 (0..19)
            ulonglong2 e = Ep[j];
            ulonglong2 o = Op[j];
            #pragma unroll
            for (int h = 0; h < 2; ++h) {
                const int p = 2 * j + h;
                const ull ev = h ? e.y : e.x;
                const ull ov = h ? o.y : o.x;
                #pragma unroll
                for (int d = 0; d < 4; ++d) {    // d = i/2
                    if (p - d >= 0 && p - d <= 15) {
                        FMA2(acc[2 * d],     ev, w2p[p - d]);
                        FMA2(acc[2 * d + 1], ov, w2p[p - d]);
                    }
                }
            }
        }

        // tanh(z) = 1 - 2/(e^{2z}+1); acc holds 2z*log2(e) split lo/hi
        float pr[8];
        {
            float arg, u, r;
            #define FIN(ac, dst)                                               \
                arg = __uint_as_float((unsigned)(ac)) +                        \
                      __uint_as_float((unsigned)((ac) >> 32));                 \
                asm("ex2.approx.f32 %0, %1;" : "=f"(u) : "f"(arg));            \
                asm("rcp.approx.f32 %0, %1;" : "=f"(r) : "f"(u + 1.0f));       \
                dst = fmaf(n2s, r, svv);
            #pragma unroll
            for (int i = 0; i < 8; ++i) { FIN(acc[i], pr[i]); }
            #undef FIN
        }

        // Two depth-4 folded reductions (proven block), quads A then B
        #pragma unroll
        for (int g2 = 0; g2 < 2; ++g2) {
            float p0 = pr[4 * g2 + 0], p1 = pr[4 * g2 + 1];
            float p2 = pr[4 * g2 + 2], p3 = pr[4 * g2 + 3];
            float s0 = p0 + __shfl_xor_sync(0xffffffffu, p0, 16);
            float s1 = p1 + __shfl_xor_sync(0xffffffffu, p1, 16);
            float s2 = p2 + __shfl_xor_sync(0xffffffffu, p2, 16);
            float s3 = p3 + __shfl_xor_sync(0xffffffffu, p3, 16);
            float q0 = (lane < 16) ? s0 : s2;
            float q1 = (lane < 16) ? s1 : s3;
            float u0 = q0 + __shfl_xor_sync(0xffffffffu, q0, 8);
            float u1 = q1 + __shfl_xor_sync(0xffffffffu, q1, 8);
            float v  = (lane & 8) ? u1 : u0;
            v += __shfl_xor_sync(0xffffffffu, v, 4);
            if ((lane & 4) == 0)
                ((float*)&Wsum4[warp][tb + 4 * g2 + (lane >> 3)])[lane & 3] = v;
        }
    }
    __syncthreads();

    // -------- Epilogue: write energies + per-tile softmax partials --------
    float e_val = NEGINF;
    if (tid < n) {
        float s = 0.f;
        #pragma unroll
        for (int w = 0; w < 8; ++w) {
            float4 f = Wsum4[w][tid];
            s += (f.x + f.y) + (f.z + f.w);
        }
        g_energy[b * TT_ + t0 + tid] = s;
        e_val = s;
    }
    // block max over e_val
    float m = e_val;
    #pragma unroll
    for (int o = 16; o; o >>= 1) m = fmaxf(m, __shfl_xor_sync(0xffffffffu, m, o));
    if (lane == 0) s_red[warp] = m;
    __syncthreads();
    if (tid < 32) {
        float v = (tid < 8) ? s_red[tid] : NEGINF;
        #pragma unroll
        for (int o = 4; o; o >>= 1) v = fmaxf(v, __shfl_xor_sync(0xffffffffu, v, o));
        if (tid == 0) s_m = v;
    }
    __syncthreads();
    const float tmax = s_m;
    float es = (tid < n) ? __expf(e_val - tmax) : 0.f;
    #pragma unroll
    for (int o = 16; o; o >>= 1) es += __shfl_xor_sync(0xffffffffu, es, o);
    if (lane == 0) s_red[warp] = es;
    __syncthreads();
    if (tid == 0) {
        float v = 0.f;
        #pragma unroll
        for (int w = 0; w < 8; ++w) v += s_red[w];
        g_pmax[b * NTIL + tix] = tmax;
        g_psum[b * NTIL + tix] = v;
    }
}

// ---------------------------------------------------------------------------
// Normalize (PDL secondary): float4 path, grid (2, BB), 256 threads.
// Thread handles 4 consecutive t. pw prefetched before gridDepSync.
// Masked entries exact 0 (matches reference).
// ---------------------------------------------------------------------------
__global__ __launch_bounds__(256) void normalize_kernel(
    const float* __restrict__ pw,
    const int*   __restrict__ lens,
    float*       __restrict__ out) {

    __shared__ float s_M, s_inv;
    const int b   = blockIdx.y;
    const int sl  = blockIdx.x;                  // 0..1, 1000 t each
    const int tid = threadIdx.x;

    const int len  = lens[b];
    const int live = (len + TILE - 1) / TILE;
    const int t    = sl * 1000 + tid * 4;
    const bool valid = (tid < 250);
    float4 pv = make_float4(0.f, 0.f, 0.f, 0.f);
    if (valid) pv = *(const float4*)(pw + b * TT_ + t);

    cudaGridDependencySynchronize();

    if (b == 0 && sl == 0 && tid == 0) g_w2_done = 0;   // reset for replay

    float4 ev = make_float4(0.f, 0.f, 0.f, 0.f);
    if (valid) ev = *(const float4*)(g_energy + b * TT_ + t);

    if (tid < 32) {
        float pm = (tid < live) ? g_pmax[b * NTIL + tid] : NEGINF;
        float M = pm;
        #pragma unroll
        for (int o = 16; o; o >>= 1) M = fmaxf(M, __shfl_xor_sync(0xffffffffu, M, o));
        float ps = (tid < live) ? g_psum[b * NTIL + tid] * __expf(pm - M) : 0.f;
        #pragma unroll
        for (int o = 16; o; o >>= 1) ps += __shfl_xor_sync(0xffffffffu, ps, o);
        if (tid == 0) { s_M = M; s_inv = 1.0f / ps; }
    }
    __syncthreads();
    const float M = s_M, inv = s_inv;

    if (valid) {
        float4 w;
        w.x = (t + 0 < len) ? __expf(ev.x - M) * inv : 0.f;
        w.y = (t + 1 < len) ? __expf(ev.y - M) * inv : 0.f;
        w.z = (t + 2 < len) ? __expf(ev.z - M) * inv : 0.f;
        w.w = (t + 3 < len) ? __expf(ev.w - M) * inv : 0.f;
        *(float4*)(out + b * TT_ + t) = w;
        float4 nw = make_float4(w.x + pv.x, w.y + pv.y, w.z + pv.z, w.w + pv.w);
        *(float4*)(out + BB * TT_ + b * TT_ + t) = nw;
    }
}

// ---------------------------------------------------------------------------
extern "C" void kernel_launch(void* const* d_in, const int* in_sizes, int n_in,
                              void* d_out, int out_size) {
    const float* query  = (const float*)d_in[0];
    const float* prevw  = (const float*)d_in[1];
    const float* wmem   = (const float*)d_in[2];
    const int*   lens   = (const int*)  d_in[3];
    const float* convw  = (const float*)d_in[4];
    const float* convb  = (const float*)d_in[5];
    const float* locw   = (const float*)d_in[6];
    const float* scorev = (const float*)d_in[7];
    const float* scoreb = (const float*)d_in[8];
    float* out = (float*)d_out;

    energy_kernel<<<NTILES, 256>>>(query, prevw, wmem, lens, convw, convb, locw,
                                   scorev, scoreb);

    cudaLaunchConfig_t cfg = {};
    cfg.gridDim  = dim3(2, BB);
    cfg.blockDim = dim3(256);
    cfg.stream   = 0;
    cudaLaunchAttribute attr[1];
    attr[0].id = cudaLaunchAttributeProgrammaticStreamSerialization;
    attr[0].val.programmaticStreamSerializationAllowed = 1;
    cfg.attrs    = attr;
    cfg.numAttrs = 1;
    cudaLaunchKernelEx(&cfg, normalize_kernel, prevw, lens, out);
}